// round 1
// baseline (speedup 1.0000x reference)
#include <cuda_runtime.h>

typedef unsigned long long ull;

#define N_NODES 20000
#define N_EDGES 4000
#define IN_DIM  128
#define OUT_DIM 64
#define NUM_HEADS 8
#define VDIM 72          // 8 expn cols + 64 weighted cols
#define ALPHA 0.2f

// edge-accumulation kernel tiling
#define NS  25           // N splits (deterministic partials)
#define NPS 800          // nodes per split (25*800 = 20000)
#define BE  64           // edges per block
#define NBE 63           // ceil(4000/64)
#define NCH 16           // node chunk in smem

// scatter-back kernel tiling
#define BN 32            // nodes per block (625 blocks exact)
#define EC 32            // edge chunk in smem

// ------------------------- scratch (static, no allocs) -------------------------
__device__ float g_xh[N_NODES * OUT_DIM];
__device__ float g_s[N_NODES * NUM_HEADS];
__device__ int   g_maxbits[NUM_HEADS];
__device__ float g_v[N_NODES * VDIM];
__device__ float g_part[NS * N_EDGES * VDIM];
__device__ float g_agg[N_EDGES * OUT_DIM];

// ------------------------- packed fp32 helpers -------------------------
__device__ __forceinline__ void fma2(ull &acc, ull a, ull b) {
    // acc = a*b + acc on packed f32x2 (Blackwell FFMA2; PTX-only)
    asm("fma.rn.f32x2 %0, %1, %2, %0;" : "+l"(acc) : "l"(a), "l"(b));
}
__device__ __forceinline__ float2 unpack2(ull v) {
    float2 f;
    asm("mov.b64 {%0, %1}, %2;" : "=f"(f.x), "=f"(f.y) : "l"(v));
    return f;
}

// ------------------------- kernels -------------------------
__global__ void k_init() {
    if (threadIdx.x < NUM_HEADS) g_maxbits[threadIdx.x] = 0xFF800000; // -inf bits
}

// Xh = X@W, s = leaky(Xh . a), global per-head max via exact atomics
__global__ void k_xh(const float* __restrict__ X, const float* __restrict__ W,
                     const float* __restrict__ att) {
    __shared__ float Xs[4][IN_DIM];
    __shared__ int sred[NUM_HEADS];
    int t = threadIdx.x;
    int n0 = blockIdx.x * 4;
    if (t < NUM_HEADS) sred[t] = 0xFF800000;
    for (int i = t; i < 4 * IN_DIM; i += 256)
        Xs[i >> 7][i & 127] = X[(n0 + (i >> 7)) * IN_DIM + (i & 127)];
    __syncthreads();
    int nl = t >> 6, j = t & 63;
    float acc = 0.f;
    #pragma unroll 8
    for (int k = 0; k < IN_DIM; k++)
        acc += Xs[nl][k] * __ldg(&W[k * OUT_DIM + j]);
    g_xh[(n0 + nl) * OUT_DIM + j] = acc;
    int h = j >> 3, d = j & 7;
    float aval = __ldg(&att[h * 16 + d]) + __ldg(&att[h * 16 + 8 + d]);
    float c = acc * aval;
    c += __shfl_down_sync(0xffffffffu, c, 4, 8);
    c += __shfl_down_sync(0xffffffffu, c, 2, 8);
    c += __shfl_down_sync(0xffffffffu, c, 1, 8);
    if (d == 0) {
        float s = c > 0.f ? c : ALPHA * c;
        g_s[(n0 + nl) * NUM_HEADS + h] = s;
        if (s >= 0.f) atomicMax(&sred[h], __float_as_int(s));
        else          atomicMin((unsigned int*)&sred[h], __float_as_uint(s));
    }
    __syncthreads();
    if (t < NUM_HEADS) {
        float s = __int_as_float(sred[t]);
        if (s >= 0.f) atomicMax(&g_maxbits[t], __float_as_int(s));
        else          atomicMin((unsigned int*)&g_maxbits[t], __float_as_uint(s));
    }
}

// V[n][0..7] = expn per head; V[n][8+j] = expn * Xh
__global__ void k_v() {
    int idx = blockIdx.x * 256 + threadIdx.x;
    if (idx >= N_NODES * VDIM) return;
    int n = idx / VDIM, c = idx - n * VDIM;
    int h = (c < 8) ? c : ((c - 8) >> 3);
    float e = expf(g_s[n * NUM_HEADS + h] - __int_as_float(g_maxbits[h]));
    float v = (c < 8) ? e : e * g_xh[n * OUT_DIM + (c - 8)];
    g_v[idx] = v;
}

// partial[e][72] += H[n][e] * V[n][72] over a node-split. Deterministic (no atomics).
// Thread tile: 8 e (4 f32x2 pairs over e) x 6 j. 96 threads = 8 e-groups x 12 j-groups.
__global__ void k_edge(const int* __restrict__ H) {
    int eb = blockIdx.x % NBE;
    int split = blockIdx.x / NBE;
    int e0 = eb * BE;
    int nbase = split * NPS;
    int t = threadIdx.x;              // 96
    int jg = t % 12, eg = t / 12;     // jg 0..11, eg 0..7
    int ebt = eg * 8;
    __shared__ float  Hs[NCH][BE];        // mask as float
    __shared__ float2 Vs[NCH][VDIM];      // V duplicated for f32x2

    ull acc[6][4];                    // [jj][e-pair]
    #pragma unroll
    for (int a = 0; a < 6; a++)
        #pragma unroll
        for (int b = 0; b < 4; b++) acc[a][b] = 0ull;

    for (int ch = 0; ch < NPS / NCH; ch++) {
        int nb = nbase + ch * NCH;
        __syncthreads();
        for (int i = t; i < NCH * BE; i += 96) {
            int nn = i >> 6, ee = i & 63;
            int e = e0 + ee;
            Hs[nn][ee] = (e < N_EDGES) ? ((H[(nb + nn) * N_EDGES + e] > 0) ? 1.f : 0.f) : 0.f;
        }
        for (int i = t; i < NCH * VDIM; i += 96) {
            int nn = i / VDIM, jj = i - nn * VDIM;
            float v = g_v[(nb + nn) * VDIM + jj];
            Vs[nn][jj] = make_float2(v, v);
        }
        __syncthreads();
        #pragma unroll
        for (int nn = 0; nn < NCH; nn++) {
            ull hp[4], vd[6];
            #pragma unroll
            for (int ep = 0; ep < 4; ep++)
                hp[ep] = *(const ull*)&Hs[nn][ebt + 2 * ep];
            #pragma unroll
            for (int jj = 0; jj < 6; jj++)
                vd[jj] = *(const ull*)&Vs[nn][jj * 12 + jg];   // strided j: conflict-free
            #pragma unroll
            for (int jj = 0; jj < 6; jj++)
                #pragma unroll
                for (int ep = 0; ep < 4; ep++)
                    fma2(acc[jj][ep], hp[ep], vd[jj]);
        }
    }
    #pragma unroll
    for (int ep = 0; ep < 4; ep++) {
        int e = e0 + ebt + 2 * ep;
        #pragma unroll
        for (int jj = 0; jj < 6; jj++) {
            float2 f = unpack2(acc[jj][ep]);
            int col = jj * 12 + jg;
            if (e < N_EDGES)     g_part[(split * N_EDGES + e)     * VDIM + col] = f.x;
            if (e + 1 < N_EDGES) g_part[(split * N_EDGES + e + 1) * VDIM + col] = f.y;
        }
    }
}

// reduce partials (fixed order) and form agg = num/denom (guarded)
__global__ void k_agg() {
    int idx = blockIdx.x * 256 + threadIdx.x;
    if (idx >= N_EDGES * OUT_DIM) return;
    int e = idx >> 6, j = idx & 63, h = j >> 3;
    float den = 0.f, num = 0.f;
    for (int s = 0; s < NS; s++) {
        const float* p = &g_part[(s * N_EDGES + e) * VDIM];
        den += p[h];
        num += p[8 + j];
    }
    g_agg[idx] = (den > 0.f) ? num / den : 0.f;
}

// out[n][64] = sum_e H[n][e] * agg[e][64] + bias
// Thread tile: 4 n x 8 j (4 f32x2 pairs over j). 64 threads = 8 n-groups x 8 j-groups.
__global__ void k_out(const int* __restrict__ H, const float* __restrict__ bias,
                      float* __restrict__ out) {
    int n0 = blockIdx.x * BN;
    int t = threadIdx.x;              // 64
    int jg = t & 7, ng = t >> 3;      // jg 0..7, ng 0..7
    int nbt = ng * 4;
    __shared__ float  Aggs[EC][OUT_DIM];
    __shared__ float2 Hs2[EC][BN + 1];    // +1 pad kills STS bank conflicts

    ull acc[4][4];                    // [tn][j-pair]
    #pragma unroll
    for (int a = 0; a < 4; a++)
        #pragma unroll
        for (int b = 0; b < 4; b++) acc[a][b] = 0ull;

    for (int ch = 0; ch < N_EDGES / EC; ch++) {
        int e0 = ch * EC;
        __syncthreads();
        for (int i = t; i < EC * OUT_DIM; i += 64)
            Aggs[i >> 6][i & 63] = g_agg[(e0 + (i >> 6)) * OUT_DIM + (i & 63)];
        for (int i = t; i < BN * EC; i += 64) {
            int nn = i >> 5, ee = i & 31;
            float h = (H[(n0 + nn) * N_EDGES + e0 + ee] > 0) ? 1.f : 0.f;
            Hs2[ee][nn] = make_float2(h, h);
        }
        __syncthreads();
        #pragma unroll 4
        for (int ee = 0; ee < EC; ee++) {
            ull hp[4], ap[4];
            #pragma unroll
            for (int tn = 0; tn < 4; tn++)
                hp[tn] = *(const ull*)&Hs2[ee][nbt + tn];
            #pragma unroll
            for (int jp = 0; jp < 4; jp++)
                ap[jp] = *(const ull*)&Aggs[ee][jp * 16 + jg * 2];  // conflict-free stride
            #pragma unroll
            for (int tn = 0; tn < 4; tn++)
                #pragma unroll
                for (int jp = 0; jp < 4; jp++)
                    fma2(acc[tn][jp], hp[tn], ap[jp]);
        }
    }
    #pragma unroll
    for (int tn = 0; tn < 4; tn++) {
        int n = n0 + nbt + tn;
        #pragma unroll
        for (int jp = 0; jp < 4; jp++) {
            float2 f = unpack2(acc[tn][jp]);
            int j = jp * 16 + jg * 2;
            out[n * OUT_DIM + j]     = f.x + __ldg(&bias[j]);
            out[n * OUT_DIM + j + 1] = f.y + __ldg(&bias[j + 1]);
        }
    }
}

// ------------------------- launch -------------------------
extern "C" void kernel_launch(void* const* d_in, const int* in_sizes, int n_in,
                              void* d_out, int out_size) {
    const float* X    = (const float*)d_in[0];
    const int*   H    = (const int*)  d_in[1];
    const float* W    = (const float*)d_in[2];
    const float* att  = (const float*)d_in[3];
    const float* bias = (const float*)d_in[4];
    float* out = (float*)d_out;

    k_init<<<1, 32>>>();
    k_xh  <<<N_NODES / 4, 256>>>(X, W, att);
    k_v   <<<(N_NODES * VDIM) / 256, 256>>>();
    k_edge<<<NS * NBE, 96>>>(H);
    k_agg <<<(N_EDGES * OUT_DIM) / 256, 256>>>();
    k_out <<<N_NODES / BN, 64>>>(H, bias, out);
}

// round 2
// speedup vs baseline: 1.7477x; 1.7477x over previous
#include <cuda_runtime.h>
#include <cuda_bf16.h>
#include <cstdint>

#define N_NODES 20000
#define N_EDGES 4000
#define IN_DIM  128
#define OUT_DIM 64
#define NUM_HEADS 8
#define ALPHA 0.2f

// GEMM1 (edge aggregation) tiling
#define NS   25          // deterministic split-K partials over nodes
#define NPS  800         // nodes per split
#define BE1  128         // edges per block
#define NEB1 32          // e-blocks (covers 4096, padded)
#define EPAD 4096
#define MROWS 80         // 72 V-cols padded to 80 (5 warps x m16)

// ------------------------- scratch (static, no allocs; zero-initialized) ----
__device__ float g_xh[N_NODES * OUT_DIM];
__device__ float g_s[N_NODES * NUM_HEADS];
__device__ int   g_maxbits[NUM_HEADS];
__device__ __nv_bfloat16 g_vhi[MROWS * N_NODES];   // [j][n], rows 72..79 stay zero
__device__ __nv_bfloat16 g_vlo[MROWS * N_NODES];
__device__ float g_part[NS * MROWS * EPAD];        // [split][j][e]
__device__ __nv_bfloat16 g_agghi[N_EDGES * OUT_DIM];  // [e][j]
__device__ __nv_bfloat16 g_agglo[N_EDGES * OUT_DIM];

// ------------------------- mma helpers -------------------------
__device__ __forceinline__ uint32_t smaddr(const void* p) {
    return (uint32_t)__cvta_generic_to_shared(p);
}
__device__ __forceinline__ void ldsm4(uint32_t* r, uint32_t a) {
    asm volatile("ldmatrix.sync.aligned.m8n8.x4.shared.b16 {%0,%1,%2,%3}, [%4];"
                 : "=r"(r[0]), "=r"(r[1]), "=r"(r[2]), "=r"(r[3]) : "r"(a));
}
__device__ __forceinline__ void ldsm4t(uint32_t* r, uint32_t a) {
    asm volatile("ldmatrix.sync.aligned.m8n8.x4.trans.shared.b16 {%0,%1,%2,%3}, [%4];"
                 : "=r"(r[0]), "=r"(r[1]), "=r"(r[2]), "=r"(r[3]) : "r"(a));
}
__device__ __forceinline__ void mma16816(float* c, const uint32_t* a, const uint32_t* b) {
    asm volatile("mma.sync.aligned.m16n8k16.row.col.f32.bf16.bf16.f32 "
                 "{%0,%1,%2,%3}, {%4,%5,%6,%7}, {%8,%9}, {%0,%1,%2,%3};"
                 : "+f"(c[0]), "+f"(c[1]), "+f"(c[2]), "+f"(c[3])
                 : "r"(a[0]), "r"(a[1]), "r"(a[2]), "r"(a[3]), "r"(b[0]), "r"(b[1]));
}
__device__ __forceinline__ uint32_t pack_mask2(int h0, int h1) {
    return (h0 > 0 ? 0x3F80u : 0u) | ((h1 > 0 ? 0x3F80u : 0u) << 16);
}

// ------------------------- small kernels -------------------------
__global__ void k_init() {
    if (threadIdx.x < NUM_HEADS) g_maxbits[threadIdx.x] = 0xFF800000;
}

// Xh = X@W, s = leaky(Xh . a), global per-head max via exact int atomics
__global__ void k_xh(const float* __restrict__ X, const float* __restrict__ W,
                     const float* __restrict__ att) {
    __shared__ float Xs[4][IN_DIM];
    __shared__ int sred[NUM_HEADS];
    int t = threadIdx.x;
    int n0 = blockIdx.x * 4;
    if (t < NUM_HEADS) sred[t] = 0xFF800000;
    for (int i = t; i < 4 * IN_DIM; i += 256)
        Xs[i >> 7][i & 127] = X[(n0 + (i >> 7)) * IN_DIM + (i & 127)];
    __syncthreads();
    int nl = t >> 6, j = t & 63;
    float acc = 0.f;
    #pragma unroll 8
    for (int k = 0; k < IN_DIM; k++)
        acc += Xs[nl][k] * __ldg(&W[k * OUT_DIM + j]);
    g_xh[(n0 + nl) * OUT_DIM + j] = acc;
    int h = j >> 3, d = j & 7;
    float aval = __ldg(&att[h * 16 + d]) + __ldg(&att[h * 16 + 8 + d]);
    float c = acc * aval;
    c += __shfl_down_sync(0xffffffffu, c, 4, 8);
    c += __shfl_down_sync(0xffffffffu, c, 2, 8);
    c += __shfl_down_sync(0xffffffffu, c, 1, 8);
    if (d == 0) {
        float s = c > 0.f ? c : ALPHA * c;
        g_s[(n0 + nl) * NUM_HEADS + h] = s;
        if (s >= 0.f) atomicMax(&sred[h], __float_as_int(s));
        else          atomicMin((unsigned int*)&sred[h], __float_as_uint(s));
    }
    __syncthreads();
    if (t < NUM_HEADS) {
        float s = __int_as_float(sred[t]);
        if (s >= 0.f) atomicMax(&g_maxbits[t], __float_as_int(s));
        else          atomicMin((unsigned int*)&g_maxbits[t], __float_as_uint(s));
    }
}

// V rows (j-major, transposed): cols 0..7 expn, 8..71 expn*Xh; hi/lo bf16 split
__global__ void k_v() {
    int n = blockIdx.x * 256 + threadIdx.x;
    if (n >= N_NODES) return;
    float ex[8];
    #pragma unroll
    for (int h = 0; h < 8; h++)
        ex[h] = expf(g_s[n * 8 + h] - __int_as_float(g_maxbits[h]));
    #pragma unroll 8
    for (int c = 0; c < 72; c++) {
        float v = (c < 8) ? ex[c] : ex[(c - 8) >> 3] * g_xh[n * 64 + (c - 8)];
        __nv_bfloat16 hi = __float2bfloat16(v);
        float lo = v - __bfloat162float(hi);
        g_vhi[c * N_NODES + n] = hi;
        g_vlo[c * N_NODES + n] = __float2bfloat16(lo);
    }
}

// ---------------- GEMM1: part[split] += V2^T(80 x 32k) @ H(32k x 128e) ------
// A = Vhi/Vlo [j][n] (row-major m x k), B = H [n][e] (k x n, ldmatrix.trans)
__global__ void k_edge_mma(const int* __restrict__ H) {
    int eb = blockIdx.x & 31, split = blockIdx.x >> 5;
    int e0 = eb * BE1;
    int t = threadIdx.x, lane = t & 31, w = t >> 5;   // 5 warps
    __shared__ __align__(16) unsigned short Ahi[MROWS * 40];  // stride 80B
    __shared__ __align__(16) unsigned short Alo[MROWS * 40];
    __shared__ __align__(16) unsigned short Hsm[32 * 136];    // stride 272B

    float c[16][4];
    #pragma unroll
    for (int f = 0; f < 16; f++)
        #pragma unroll
        for (int q = 0; q < 4; q++) c[f][q] = 0.f;

    for (int ch = 0; ch < NPS / 32; ch++) {
        int nb = split * NPS + ch * 32;
        __syncthreads();
        // H tile: 32 nodes x 128 edges, int -> bf16 {0,1}
        for (int i = t; i < 1024; i += 160) {
            int r = i >> 5, c4 = i & 31;
            int e = e0 + c4 * 4;
            uint2 v = make_uint2(0u, 0u);
            if (e < N_EDGES) {
                int4 h4 = *reinterpret_cast<const int4*>(&H[(nb + r) * N_EDGES + e]);
                v.x = pack_mask2(h4.x, h4.y);
                v.y = pack_mask2(h4.z, h4.w);
            }
            *reinterpret_cast<uint2*>(&Hsm[r * 136 + c4 * 4]) = v;
        }
        // A tiles: 80 rows x 32 n
        for (int i = t; i < 640; i += 160) {
            int r = i >> 3, cc = i & 7;
            *reinterpret_cast<uint2*>(&Ahi[r * 40 + cc * 4]) =
                *reinterpret_cast<const uint2*>(&g_vhi[r * N_NODES + nb + cc * 4]);
            *reinterpret_cast<uint2*>(&Alo[r * 40 + cc * 4]) =
                *reinterpret_cast<const uint2*>(&g_vlo[r * N_NODES + nb + cc * 4]);
        }
        __syncthreads();
        #pragma unroll
        for (int ks = 0; ks < 2; ks++) {
            uint32_t ah[4], al[4];
            int arow = w * 16 + (lane & 15);
            int acol = ks * 16 + (lane >> 4) * 8;
            ldsm4(ah, smaddr(&Ahi[arow * 40 + acol]));
            ldsm4(al, smaddr(&Alo[arow * 40 + acol]));
            int brow = ks * 16 + (lane & 15);
            #pragma unroll
            for (int ef = 0; ef < 8; ef++) {
                uint32_t b[4];
                ldsm4t(b, smaddr(&Hsm[brow * 136 + ef * 16 + (lane >> 4) * 8]));
                mma16816(c[2 * ef],     ah, b);
                mma16816(c[2 * ef],     al, b);
                mma16816(c[2 * ef + 1], ah, b + 2);
                mma16816(c[2 * ef + 1], al, b + 2);
            }
        }
    }
    // epilogue: part[split][j][e]
    int jr = w * 16 + (lane >> 2);
    int ec = e0 + (lane & 3) * 2;
    #pragma unroll
    for (int f = 0; f < 16; f++) {
        int e = ec + (f >> 1) * 16 + (f & 1) * 8;
        *reinterpret_cast<float2*>(&g_part[(split * MROWS + jr) * EPAD + e]) =
            make_float2(c[f][0], c[f][1]);
        *reinterpret_cast<float2*>(&g_part[(split * MROWS + jr + 8) * EPAD + e]) =
            make_float2(c[f][2], c[f][3]);
    }
}

// ------------- reduce partials + agg = num/den + hi/lo split ---------------
__global__ void k_agg() {
    __shared__ float num[64][65];
    __shared__ float den[64][9];
    int e0 = blockIdx.x * 64;
    int t = threadIdx.x;
    for (int idx = t; idx < 64 * 72; idx += 256) {
        int e_l = idx & 63, col = idx >> 6;
        float s = 0.f;
        #pragma unroll
        for (int sp = 0; sp < NS; sp++)
            s += g_part[(sp * MROWS + col) * EPAD + e0 + e_l];
        if (col < 8) den[e_l][col] = s; else num[e_l][col - 8] = s;
    }
    __syncthreads();
    for (int idx = t; idx < 4096; idx += 256) {
        int j = idx & 63, e_l = idx >> 6;
        int e = e0 + e_l;
        if (e < N_EDGES) {
            float d = den[e_l][j >> 3];
            float v = (d > 0.f) ? num[e_l][j] / d : 0.f;
            __nv_bfloat16 hi = __float2bfloat16(v);
            g_agghi[e * 64 + j] = hi;
            g_agglo[e * 64 + j] = __float2bfloat16(v - __bfloat162float(hi));
        }
    }
}

// ---------------- GEMM2: out(128n x 64j) = H(n x e) @ agg2(e x j) ----------
// A = H [n][e] row-major, B = agghi/agglo [e][j] via ldmatrix.trans
__global__ void k_out_mma(const int* __restrict__ H, const float* __restrict__ bias,
                          float* __restrict__ out) {
    int n0 = blockIdx.x * 128;
    int t = threadIdx.x, lane = t & 31, w = t >> 5;   // 8 warps
    __shared__ __align__(16) unsigned short Hsm[128 * 40];  // stride 80B
    __shared__ __align__(16) unsigned short Bh[32 * 72];    // stride 144B
    __shared__ __align__(16) unsigned short Bl[32 * 72];

    float c[8][4];
    #pragma unroll
    for (int f = 0; f < 8; f++)
        #pragma unroll
        for (int q = 0; q < 4; q++) c[f][q] = 0.f;

    for (int ch = 0; ch < N_EDGES / 32; ch++) {
        int e0 = ch * 32;
        __syncthreads();
        for (int i = t; i < 1024; i += 256) {
            int r = i >> 3, c4 = i & 7;
            int n = n0 + r;
            uint2 v = make_uint2(0u, 0u);
            if (n < N_NODES) {
                int4 h4 = *reinterpret_cast<const int4*>(&H[n * N_EDGES + e0 + c4 * 4]);
                v.x = pack_mask2(h4.x, h4.y);
                v.y = pack_mask2(h4.z, h4.w);
            }
            *reinterpret_cast<uint2*>(&Hsm[r * 40 + c4 * 4]) = v;
        }
        for (int i = t; i < 512; i += 256) {
            int r = i >> 4, cc = i & 15;
            *reinterpret_cast<uint2*>(&Bh[r * 72 + cc * 4]) =
                *reinterpret_cast<const uint2*>(&g_agghi[(e0 + r) * 64 + cc * 4]);
            *reinterpret_cast<uint2*>(&Bl[r * 72 + cc * 4]) =
                *reinterpret_cast<const uint2*>(&g_agglo[(e0 + r) * 64 + cc * 4]);
        }
        __syncthreads();
        #pragma unroll
        for (int ks = 0; ks < 2; ks++) {
            uint32_t a[4];
            int arow = w * 16 + (lane & 15);
            ldsm4(a, smaddr(&Hsm[arow * 40 + ks * 16 + (lane >> 4) * 8]));
            int brow = ks * 16 + (lane & 15);
            #pragma unroll
            for (int nf = 0; nf < 4; nf++) {
                uint32_t bh[4], bl[4];
                ldsm4t(bh, smaddr(&Bh[brow * 72 + nf * 16 + (lane >> 4) * 8]));
                ldsm4t(bl, smaddr(&Bl[brow * 72 + nf * 16 + (lane >> 4) * 8]));
                mma16816(c[2 * nf],     a, bh);
                mma16816(c[2 * nf],     a, bl);
                mma16816(c[2 * nf + 1], a, bh + 2);
                mma16816(c[2 * nf + 1], a, bl + 2);
            }
        }
    }
    int n = n0 + w * 16 + (lane >> 2);
    int jb = (lane & 3) * 2;
    #pragma unroll
    for (int f = 0; f < 8; f++) {
        int j = (f >> 1) * 16 + (f & 1) * 8 + jb;
        float b0 = __ldg(&bias[j]), b1 = __ldg(&bias[j + 1]);
        if (n < N_NODES)
            *reinterpret_cast<float2*>(&out[n * 64 + j]) =
                make_float2(c[f][0] + b0, c[f][1] + b1);
        if (n + 8 < N_NODES)
            *reinterpret_cast<float2*>(&out[(n + 8) * 64 + j]) =
                make_float2(c[f][2] + b0, c[f][3] + b1);
    }
}

// ------------------------- launch -------------------------
extern "C" void kernel_launch(void* const* d_in, const int* in_sizes, int n_in,
                              void* d_out, int out_size) {
    const float* X    = (const float*)d_in[0];
    const int*   H    = (const int*)  d_in[1];
    const float* W    = (const float*)d_in[2];
    const float* att  = (const float*)d_in[3];
    const float* bias = (const float*)d_in[4];
    float* out = (float*)d_out;

    k_init    <<<1, 32>>>();
    k_xh      <<<N_NODES / 4, 256>>>(X, W, att);
    k_v       <<<(N_NODES + 255) / 256, 256>>>();
    k_edge_mma<<<NS * NEB1, 160>>>(H);
    k_agg     <<<(N_EDGES + 63) / 64, 256>>>();
    k_out_mma <<<(N_NODES + 127) / 128, 256>>>(H, bias, out);
}

// round 9
// speedup vs baseline: 3.1053x; 1.7768x over previous
#include <cuda_runtime.h>
#include <cuda_bf16.h>
#include <cstdint>

#define N_NODES 20000
#define N_EDGES 4000
#define IN_DIM  128
#define OUT_DIM 64
#define NUM_HEADS 8
#define ALPHA 0.2f

#define NS   25          // GEMM1 deterministic node splits
#define NPS  800
#define EPAD 4096
#define MROWS 80         // 72 V-rows padded to 80 (5 warps x m16)
#define HW_WORDS 125     // 4000 edges / 32 bits
#define KS2  5           // GEMM2 deterministic edge splits
#define NB2  157         // ceil(20000/128)

// ---------------- scratch (static, zero-init, no allocs) ----------------
__device__ float g_xh[N_NODES * OUT_DIM];
__device__ float g_s[N_NODES * NUM_HEADS];
__device__ int   g_maxbits[NUM_HEADS];
__device__ uint32_t g_hbits[N_NODES * HW_WORDS];
__device__ __nv_bfloat16 g_whi[IN_DIM * OUT_DIM], g_wlo[IN_DIM * OUT_DIM];
__device__ __nv_bfloat16 g_vhi[MROWS * N_NODES], g_vlo[MROWS * N_NODES];
__device__ float g_part[NS * MROWS * EPAD];
__device__ __nv_bfloat16 g_agghi[N_EDGES * OUT_DIM], g_agglo[N_EDGES * OUT_DIM];
__device__ float g_opart[KS2 * N_NODES * OUT_DIM];

// ---------------- helpers ----------------
__device__ __forceinline__ uint32_t smaddr(const void* p) {
    return (uint32_t)__cvta_generic_to_shared(p);
}
__device__ __forceinline__ void ldsm4(uint32_t* r, uint32_t a) {
    asm volatile("ldmatrix.sync.aligned.m8n8.x4.shared.b16 {%0,%1,%2,%3}, [%4];"
                 : "=r"(r[0]), "=r"(r[1]), "=r"(r[2]), "=r"(r[3]) : "r"(a));
}
__device__ __forceinline__ void ldsm4t(uint32_t* r, uint32_t a) {
    asm volatile("ldmatrix.sync.aligned.m8n8.x4.trans.shared.b16 {%0,%1,%2,%3}, [%4];"
                 : "=r"(r[0]), "=r"(r[1]), "=r"(r[2]), "=r"(r[3]) : "r"(a));
}
__device__ __forceinline__ void mma16816(float* c, const uint32_t* a, const uint32_t* b) {
    asm volatile("mma.sync.aligned.m16n8k16.row.col.f32.bf16.bf16.f32 "
                 "{%0,%1,%2,%3}, {%4,%5,%6,%7}, {%8,%9}, {%0,%1,%2,%3};"
                 : "+f"(c[0]), "+f"(c[1]), "+f"(c[2]), "+f"(c[3])
                 : "r"(a[0]), "r"(a[1]), "r"(a[2]), "r"(a[3]), "r"(b[0]), "r"(b[1]));
}
__device__ __forceinline__ void cpa16(uint32_t s, const void* g) {
    asm volatile("cp.async.cg.shared.global [%0], [%1], 16;" :: "r"(s), "l"(g));
}
__device__ __forceinline__ void cp_commit() { asm volatile("cp.async.commit_group;"); }
__device__ __forceinline__ void cp_wait0()  { asm volatile("cp.async.wait_group 0;"); }
__device__ __forceinline__ void cp_wait1()  { asm volatile("cp.async.wait_group 1;"); }

__device__ __forceinline__ void split2(float2 v, uint32_t& hi, uint32_t& lo) {
    __nv_bfloat16 hx = __float2bfloat16(v.x), hy = __float2bfloat16(v.y);
    float lx = v.x - __bfloat162float(hx), ly = v.y - __bfloat162float(hy);
    __nv_bfloat16 gx = __float2bfloat16(lx), gy = __float2bfloat16(ly);
    unsigned short uhx = *reinterpret_cast<unsigned short*>(&hx);
    unsigned short uhy = *reinterpret_cast<unsigned short*>(&hy);
    unsigned short ugx = *reinterpret_cast<unsigned short*>(&gx);
    unsigned short ugy = *reinterpret_cast<unsigned short*>(&gy);
    hi = (uint32_t)uhx | ((uint32_t)uhy << 16);
    lo = (uint32_t)ugx | ((uint32_t)ugy << 16);
}

// ---------------- small kernels ----------------
__global__ void k_init() {
    if (threadIdx.x < NUM_HEADS) g_maxbits[threadIdx.x] = 0xFF800000;
}

__global__ void k_wsplit(const float* __restrict__ W) {
    int i = blockIdx.x * 256 + threadIdx.x;
    if (i < IN_DIM * OUT_DIM) {
        float v = W[i];
        __nv_bfloat16 h = __float2bfloat16(v);
        g_whi[i] = h;
        g_wlo[i] = __float2bfloat16(v - __bfloat162float(h));
    }
}

// bit-pack H: g_hbits[n][w], bit i = (H[n][32w+i] > 0)
__global__ void k_hbits(const int* __restrict__ H) {
    int idx = blockIdx.x * 256 + threadIdx.x;
    if (idx >= N_NODES * HW_WORDS) return;
    int n = idx / HW_WORDS, w = idx - n * HW_WORDS;
    const int* p = &H[n * N_EDGES + w * 32];
    uint32_t bits = 0;
    #pragma unroll
    for (int i = 0; i < 32; i += 4) {
        int4 v = *reinterpret_cast<const int4*>(&p[i]);
        bits |= (v.x > 0 ? 1u : 0u) << i;
        bits |= (v.y > 0 ? 1u : 0u) << (i + 1);
        bits |= (v.z > 0 ? 1u : 0u) << (i + 2);
        bits |= (v.w > 0 ? 1u : 0u) << (i + 3);
    }
    g_hbits[idx] = bits;
}

// Xh = X @ W on tensor pipe (3-pass hi/lo). A frags direct from gmem, W in smem.
__global__ __launch_bounds__(256) void k_xh_mma(const float* __restrict__ X) {
    __shared__ __align__(16) unsigned short Bh[IN_DIM * 72], Bl[IN_DIM * 72];
    int t = threadIdx.x, lane = t & 31, w = t >> 5;
    int n0 = blockIdx.x * 128;
    for (int i = t; i < 2048; i += 256) {
        int m = i >> 10, r = (i & 1023) >> 3, q = i & 7;
        const __nv_bfloat16* src = (m ? g_wlo : g_whi) + r * 64 + q * 8;
        unsigned short* dst = (m ? Bl : Bh) + r * 72 + q * 8;
        *reinterpret_cast<uint4*>(dst) = *reinterpret_cast<const uint4*>(src);  // 16B = 8 bf16
    }
    __syncthreads();
    float c[8][4];
    #pragma unroll
    for (int f = 0; f < 8; f++)
        #pragma unroll
        for (int q = 0; q < 4; q++) c[f][q] = 0.f;
    int rbase = n0 + w * 16 + (lane >> 2);
    #pragma unroll
    for (int ks = 0; ks < 8; ks++) {
        int cc = ks * 16 + (lane & 3) * 2;
        float2 z = make_float2(0.f, 0.f);
        float2 x00 = rbase < N_NODES ? *reinterpret_cast<const float2*>(&X[rbase * 128 + cc]) : z;
        float2 x10 = rbase + 8 < N_NODES ? *reinterpret_cast<const float2*>(&X[(rbase + 8) * 128 + cc]) : z;
        float2 x01 = rbase < N_NODES ? *reinterpret_cast<const float2*>(&X[rbase * 128 + cc + 8]) : z;
        float2 x11 = rbase + 8 < N_NODES ? *reinterpret_cast<const float2*>(&X[(rbase + 8) * 128 + cc + 8]) : z;
        uint32_t ah[4], al[4];
        split2(x00, ah[0], al[0]); split2(x10, ah[1], al[1]);
        split2(x01, ah[2], al[2]); split2(x11, ah[3], al[3]);
        int brow = ks * 16 + (lane & 15);
        #pragma unroll
        for (int nf = 0; nf < 4; nf++) {
            uint32_t bh[4], bl[4];
            ldsm4t(bh, smaddr(&Bh[brow * 72 + nf * 16 + (lane >> 4) * 8]));
            ldsm4t(bl, smaddr(&Bl[brow * 72 + nf * 16 + (lane >> 4) * 8]));
            mma16816(c[2 * nf], ah, bh);
            mma16816(c[2 * nf], ah, bl);
            mma16816(c[2 * nf], al, bh);
            mma16816(c[2 * nf + 1], ah, bh + 2);
            mma16816(c[2 * nf + 1], ah, bl + 2);
            mma16816(c[2 * nf + 1], al, bh + 2);
        }
    }
    #pragma unroll
    for (int nf = 0; nf < 4; nf++)
        #pragma unroll
        for (int half = 0; half < 2; half++) {
            int f = 2 * nf + half, j = nf * 16 + half * 8 + (lane & 3) * 2;
            if (rbase < N_NODES)
                *reinterpret_cast<float2*>(&g_xh[rbase * 64 + j]) = make_float2(c[f][0], c[f][1]);
            if (rbase + 8 < N_NODES)
                *reinterpret_cast<float2*>(&g_xh[(rbase + 8) * 64 + j]) = make_float2(c[f][2], c[f][3]);
        }
}

// scores + exact global per-head max
__global__ void k_score(const float* __restrict__ att) {
    __shared__ float a[NUM_HEADS][8];
    __shared__ int sred[NUM_HEADS];
    int t = threadIdx.x;
    if (t < 64) a[t >> 3][t & 7] = att[(t >> 3) * 16 + (t & 7)] + att[(t >> 3) * 16 + 8 + (t & 7)];
    if (t < NUM_HEADS) sred[t] = 0xFF800000;
    __syncthreads();
    int n = blockIdx.x * 256 + t;
    if (n < N_NODES) {
        #pragma unroll
        for (int h = 0; h < NUM_HEADS; h++) {
            float s = 0.f;
            #pragma unroll
            for (int d = 0; d < 8; d++) s += g_xh[n * 64 + h * 8 + d] * a[h][d];
            s = s > 0.f ? s : ALPHA * s;
            g_s[n * NUM_HEADS + h] = s;
            if (s >= 0.f) atomicMax(&sred[h], __float_as_int(s));
            else          atomicMin((unsigned int*)&sred[h], __float_as_uint(s));
        }
    }
    __syncthreads();
    if (t < NUM_HEADS) {
        float s = __int_as_float(sred[t]);
        if (s >= 0.f) atomicMax(&g_maxbits[t], __float_as_int(s));
        else          atomicMin((unsigned int*)&g_maxbits[t], __float_as_uint(s));
    }
}

// V (transposed, j-major): rows 0..7 expn, 8..71 expn*Xh; hi/lo bf16
__global__ void k_v() {
    int n = blockIdx.x * 256 + threadIdx.x;
    if (n >= N_NODES) return;
    float ex[8];
    #pragma unroll
    for (int h = 0; h < 8; h++)
        ex[h] = expf(g_s[n * 8 + h] - __int_as_float(g_maxbits[h]));
    #pragma unroll 8
    for (int c = 0; c < 72; c++) {
        float v = (c < 8) ? ex[c] : ex[(c - 8) >> 3] * g_xh[n * 64 + (c - 8)];
        __nv_bfloat16 hi = __float2bfloat16(v);
        g_vhi[c * N_NODES + n] = hi;
        g_vlo[c * N_NODES + n] = __float2bfloat16(v - __bfloat162float(hi));
    }
}

// -------- GEMM1: part[split][j][e] = V2^T(80 x 800) @ H(800 x 128e) --------
__global__ __launch_bounds__(320) void k_edge_mma() {
    int eb = blockIdx.x & 31, split = blockIdx.x >> 5;
    int e0 = eb * 128;
    int t = threadIdx.x, lane = t & 31, w = t >> 5;
    int wm = w % 5, wn = w / 5;
    __shared__ __align__(16) unsigned short Ahi[2][MROWS * 40], Alo[2][MROWS * 40];
    __shared__ __align__(16) unsigned short Hsm[2][32 * 136];

    float c[8][4];
    #pragma unroll
    for (int f = 0; f < 8; f++)
        #pragma unroll
        for (int q = 0; q < 4; q++) c[f][q] = 0.f;

    int nb0 = split * NPS;
    auto loadA = [&](int buf, int nb) {
        for (int o = t; o < 640; o += 320) {
            int j = o >> 3, m = (o >> 2) & 1, q = o & 3;
            const __nv_bfloat16* src = (m ? g_vlo : g_vhi) + j * N_NODES + nb + q * 8;
            unsigned short* dst = (m ? Alo[buf] : Ahi[buf]) + j * 40 + q * 8;
            cpa16(smaddr(dst), src);
        }
    };
    int wordidx = eb * 4 + (t & 3);
    bool wok = (t < 128) && (wordidx < HW_WORDS);
    uint32_t hw = wok ? g_hbits[(nb0 + (t >> 2)) * HW_WORDS + wordidx] : 0u;
    loadA(0, nb0);
    cp_commit();

    for (int ch = 0; ch < 25; ch++) {
        int nb = nb0 + ch * 32;
        uint32_t hwn = 0u;
        if (ch < 24) {
            loadA((ch + 1) & 1, nb + 32);
            cp_commit();
            hwn = wok ? g_hbits[(nb + 32 + (t >> 2)) * HW_WORDS + wordidx] : 0u;
            cp_wait1();
        } else cp_wait0();
        if (t < 128) {
            unsigned short* hb = &Hsm[ch & 1][(t >> 2) * 136 + (t & 3) * 32];
            #pragma unroll
            for (int i = 0; i < 16; i++) {
                uint32_t v = (((hw >> (2 * i)) & 1u) ? 0x3F80u : 0u) |
                             (((hw >> (2 * i + 1)) & 1u) ? 0x3F800000u : 0u);
                *reinterpret_cast<uint32_t*>(hb + 2 * i) = v;
            }
        }
        __syncthreads();
        int b0 = ch & 1;
        #pragma unroll
        for (int ks = 0; ks < 2; ks++) {
            uint32_t ah[4], al[4];
            int arow = wm * 16 + (lane & 15);
            int acol = ks * 16 + (lane >> 4) * 8;
            ldsm4(ah, smaddr(&Ahi[b0][arow * 40 + acol]));
            ldsm4(al, smaddr(&Alo[b0][arow * 40 + acol]));
            int brow = ks * 16 + (lane & 15);
            #pragma unroll
            for (int nf = 0; nf < 4; nf++) {
                uint32_t b[4];
                ldsm4t(b, smaddr(&Hsm[b0][brow * 136 + wn * 64 + nf * 16 + (lane >> 4) * 8]));
                mma16816(c[2 * nf],     ah, b);
                mma16816(c[2 * nf],     al, b);
                mma16816(c[2 * nf + 1], ah, b + 2);
                mma16816(c[2 * nf + 1], al, b + 2);
            }
        }
        __syncthreads();
        hw = hwn;
    }
    int jr = wm * 16 + (lane >> 2);
    int ebase = e0 + wn * 64 + (lane & 3) * 2;
    #pragma unroll
    for (int nf = 0; nf < 4; nf++)
        #pragma unroll
        for (int half = 0; half < 2; half++) {
            int f = 2 * nf + half;
            int e = ebase + nf * 16 + half * 8;
            *reinterpret_cast<float2*>(&g_part[(split * MROWS + jr) * EPAD + e]) =
                make_float2(c[f][0], c[f][1]);
            *reinterpret_cast<float2*>(&g_part[(split * MROWS + jr + 8) * EPAD + e]) =
                make_float2(c[f][2], c[f][3]);
        }
}

// -------- reduce partials + agg = num/den + hi/lo split --------
__global__ void k_agg() {
    __shared__ float num[64][65];
    __shared__ float den[64][9];
    int e0 = blockIdx.x * 64;
    int t = threadIdx.x;
    for (int idx = t; idx < 64 * 72; idx += 256) {
        int e_l = idx & 63, col = idx >> 6;
        float s = 0.f;
        #pragma unroll
        for (int sp = 0; sp < NS; sp++)
            s += g_part[(sp * MROWS + col) * EPAD + e0 + e_l];
        if (col < 8) den[e_l][col] = s; else num[e_l][col - 8] = s;
    }
    __syncthreads();
    for (int idx = t; idx < 4096; idx += 256) {
        int j = idx & 63, e_l = idx >> 6;
        int e = e0 + e_l;
        if (e < N_EDGES) {
            float d = den[e_l][j >> 3];
            float v = (d > 0.f) ? num[e_l][j] / d : 0.f;
            __nv_bfloat16 hi = __float2bfloat16(v);
            g_agghi[e * 64 + j] = hi;
            g_agglo[e * 64 + j] = __float2bfloat16(v - __bfloat162float(hi));
        }
    }
}

// -------- GEMM2: opart[split][n][j] = H(128n x 800e) @ agg2(800e x 64j) --------
__global__ __launch_bounds__(256) void k_out_mma() {
    int nbk = blockIdx.x % NB2, split = blockIdx.x / NB2;
    int n0 = nbk * 128;
    int eb0 = split * 800;
    int t = threadIdx.x, lane = t & 31, w = t >> 5;
    __shared__ __align__(16) unsigned short Hsm[2][128 * 40];
    __shared__ __align__(16) unsigned short Bh[2][32 * 72], Bl[2][32 * 72];

    float c[8][4];
    #pragma unroll
    for (int f = 0; f < 8; f++)
        #pragma unroll
        for (int q = 0; q < 4; q++) c[f][q] = 0.f;

    auto loadB = [&](int buf, int e0) {
        for (int o = t; o < 512; o += 256) {
            int r = o >> 4, m = (o >> 3) & 1, q = o & 7;
            const __nv_bfloat16* src = (m ? g_agglo : g_agghi) + (e0 + r) * 64 + q * 8;
            unsigned short* dst = (m ? Bl[buf] : Bh[buf]) + r * 72 + q * 8;
            cpa16(smaddr(dst), src);
        }
    };
    int nrow = n0 + t;
    bool wok = (t < 128) && (nrow < N_NODES);
    uint32_t hw = wok ? g_hbits[nrow * HW_WORDS + split * 25] : 0u;
    loadB(0, eb0);
    cp_commit();

    for (int ch = 0; ch < 25; ch++) {
        uint32_t hwn = 0u;
        if (ch < 24) {
            loadB((ch + 1) & 1, eb0 + (ch + 1) * 32);
            cp_commit();
            hwn = wok ? g_hbits[nrow * HW_WORDS + split * 25 + ch + 1] : 0u;
            cp_wait1();
        } else cp_wait0();
        if (t < 128) {
            unsigned short* hb = &Hsm[ch & 1][t * 40];
            #pragma unroll
            for (int i = 0; i < 16; i++) {
                uint32_t v = (((hw >> (2 * i)) & 1u) ? 0x3F80u : 0u) |
                             (((hw >> (2 * i + 1)) & 1u) ? 0x3F800000u : 0u);
                *reinterpret_cast<uint32_t*>(hb + 2 * i) = v;
            }
        }
        __syncthreads();
        int b0 = ch & 1;
        #pragma unroll
        for (int ks = 0; ks < 2; ks++) {
            uint32_t a[4];
            int arow = w * 16 + (lane & 15);
            ldsm4(a, smaddr(&Hsm[b0][arow * 40 + ks * 16 + (lane >> 4) * 8]));
            int brow = ks * 16 + (lane & 15);
            #pragma unroll
            for (int nf = 0; nf < 4; nf++) {
                uint32_t bh[4], bl[4];
                ldsm4t(bh, smaddr(&Bh[b0][brow * 72 + nf * 16 + (lane >> 4) * 8]));
                ldsm4t(bl, smaddr(&Bl[b0][brow * 72 + nf * 16 + (lane >> 4) * 8]));
                mma16816(c[2 * nf],     a, bh);
                mma16816(c[2 * nf],     a, bl);
                mma16816(c[2 * nf + 1], a, bh + 2);
                mma16816(c[2 * nf + 1], a, bl + 2);
            }
        }
        __syncthreads();
        hw = hwn;
    }
    int n = n0 + w * 16 + (lane >> 2);
    #pragma unroll
    for (int nf = 0; nf < 4; nf++)
        #pragma unroll
        for (int half = 0; half < 2; half++) {
            int f = 2 * nf + half, j = nf * 16 + half * 8 + (lane & 3) * 2;
            if (n < N_NODES)
                *reinterpret_cast<float2*>(&g_opart[(split * N_NODES + n) * 64 + j]) =
                    make_float2(c[f][0], c[f][1]);
            if (n + 8 < N_NODES)
                *reinterpret_cast<float2*>(&g_opart[(split * N_NODES + n + 8) * 64 + j]) =
                    make_float2(c[f][2], c[f][3]);
        }
}

// -------- finalize: fixed-order split reduce + bias (bounds-guarded) --------
__global__ void k_final(const float* __restrict__ bias, float* __restrict__ out) {
    int i = blockIdx.x * 256 + threadIdx.x;   // float4 index
    if (i >= N_NODES * OUT_DIM / 4) return;   // 80000 float4s
    float4 s = *reinterpret_cast<const float4*>(&bias[(i & 15) * 4]);
    #pragma unroll
    for (int sp = 0; sp < KS2; sp++) {
        float4 v = *reinterpret_cast<const float4*>(&g_opart[sp * N_NODES * OUT_DIM + i * 4]);
        s.x += v.x; s.y += v.y; s.z += v.z; s.w += v.w;
    }
    *reinterpret_cast<float4*>(&out[i * 4]) = s;
}

// ---------------- launch ----------------
extern "C" void kernel_launch(void* const* d_in, const int* in_sizes, int n_in,
                              void* d_out, int out_size) {
    const float* X    = (const float*)d_in[0];
    const int*   H    = (const int*)  d_in[1];
    const float* W    = (const float*)d_in[2];
    const float* att  = (const float*)d_in[3];
    const float* bias = (const float*)d_in[4];
    float* out = (float*)d_out;

    k_init   <<<1, 32>>>();
    k_wsplit <<<32, 256>>>(W);
    k_hbits  <<<(N_NODES * HW_WORDS + 255) / 256, 256>>>(H);
    k_xh_mma <<<NB2, 256>>>(X);
    k_score  <<<(N_NODES + 255) / 256, 256>>>(att);
    k_v      <<<(N_NODES + 255) / 256, 256>>>();
    k_edge_mma<<<NS * 32, 320>>>();
    k_agg    <<<(N_EDGES + 63) / 64, 256>>>();
    k_out_mma<<<KS2 * NB2, 256>>>();
    k_final  <<<(N_NODES * OUT_DIM / 4 + 255) / 256, 256>>>(bias, out);
}

// round 12
// speedup vs baseline: 5.1661x; 1.6636x over previous
#include <cuda_runtime.h>
#include <cuda_bf16.h>
#include <cstdint>

#define N_NODES 20000
#define N_EDGES 4000
#define IN_DIM  128
#define OUT_DIM 64
#define NUM_HEADS 8
#define ALPHA 0.2f

#define NS   25          // GEMM1 deterministic node splits
#define NPS  800
#define EPAD 4096
#define MROWS 80         // 72 V-rows padded to 80 (5 warps x m16)
#define HW_WORDS 125     // 4000 edges / 32 bits
#define KS2  5           // GEMM2 deterministic edge splits
#define NB2  157         // ceil(20000/128)
#define PREP_WBLKS 32

// ---------------- scratch (static, zero-init, no allocs) ----------------
__device__ float g_xh[N_NODES * OUT_DIM];
__device__ float g_s[N_NODES * NUM_HEADS];
__device__ int   g_maxbits[NUM_HEADS];
__device__ uint32_t g_hbits[N_NODES * HW_WORDS];
__device__ __nv_bfloat16 g_whi[IN_DIM * OUT_DIM], g_wlo[IN_DIM * OUT_DIM];
__device__ __nv_bfloat16 g_vhi[MROWS * N_NODES], g_vlo[MROWS * N_NODES];
__device__ float g_part[NS * MROWS * EPAD];
__device__ __nv_bfloat16 g_agghi[N_EDGES * OUT_DIM], g_agglo[N_EDGES * OUT_DIM];
__device__ float g_opart[KS2 * N_NODES * OUT_DIM];

// ---------------- helpers ----------------
__device__ __forceinline__ uint32_t smaddr(const void* p) {
    return (uint32_t)__cvta_generic_to_shared(p);
}
__device__ __forceinline__ void ldsm4(uint32_t* r, uint32_t a) {
    asm volatile("ldmatrix.sync.aligned.m8n8.x4.shared.b16 {%0,%1,%2,%3}, [%4];"
                 : "=r"(r[0]), "=r"(r[1]), "=r"(r[2]), "=r"(r[3]) : "r"(a));
}
__device__ __forceinline__ void ldsm4t(uint32_t* r, uint32_t a) {
    asm volatile("ldmatrix.sync.aligned.m8n8.x4.trans.shared.b16 {%0,%1,%2,%3}, [%4];"
                 : "=r"(r[0]), "=r"(r[1]), "=r"(r[2]), "=r"(r[3]) : "r"(a));
}
__device__ __forceinline__ void mma16816(float* c, const uint32_t* a, const uint32_t* b) {
    asm volatile("mma.sync.aligned.m16n8k16.row.col.f32.bf16.bf16.f32 "
                 "{%0,%1,%2,%3}, {%4,%5,%6,%7}, {%8,%9}, {%0,%1,%2,%3};"
                 : "+f"(c[0]), "+f"(c[1]), "+f"(c[2]), "+f"(c[3])
                 : "r"(a[0]), "r"(a[1]), "r"(a[2]), "r"(a[3]), "r"(b[0]), "r"(b[1]));
}
__device__ __forceinline__ void cpa16(uint32_t s, const void* g) {
    asm volatile("cp.async.cg.shared.global [%0], [%1], 16;" :: "r"(s), "l"(g));
}
__device__ __forceinline__ void cp_commit() { asm volatile("cp.async.commit_group;"); }
__device__ __forceinline__ void cp_wait0()  { asm volatile("cp.async.wait_group 0;"); }

__device__ __forceinline__ void split2(float2 v, uint32_t& hi, uint32_t& lo) {
    __nv_bfloat16 hx = __float2bfloat16(v.x), hy = __float2bfloat16(v.y);
    float lx = v.x - __bfloat162float(hx), ly = v.y - __bfloat162float(hy);
    __nv_bfloat16 gx = __float2bfloat16(lx), gy = __float2bfloat16(ly);
    unsigned short uhx = *reinterpret_cast<unsigned short*>(&hx);
    unsigned short uhy = *reinterpret_cast<unsigned short*>(&hy);
    unsigned short ugx = *reinterpret_cast<unsigned short*>(&gx);
    unsigned short ugy = *reinterpret_cast<unsigned short*>(&gy);
    hi = (uint32_t)uhx | ((uint32_t)uhy << 16);
    lo = (uint32_t)ugx | ((uint32_t)ugy << 16);
}

// ---- prep: g_maxbits init + W hi/lo split + H bit-pack, one launch ----
__global__ void k_prep(const int* __restrict__ H, const float* __restrict__ W) {
    int b = blockIdx.x, t = threadIdx.x;
    if (b == 0 && t < NUM_HEADS) g_maxbits[t] = 0xFF800000;
    if (b < PREP_WBLKS) {
        int i = b * 256 + t;
        if (i < IN_DIM * OUT_DIM) {
            float v = W[i];
            __nv_bfloat16 h = __float2bfloat16(v);
            g_whi[i] = h;
            g_wlo[i] = __float2bfloat16(v - __bfloat162float(h));
        }
    } else {
        int idx = (b - PREP_WBLKS) * 256 + t;
        if (idx < N_NODES * HW_WORDS) {
            int n = idx / HW_WORDS, w = idx - n * HW_WORDS;
            const int* p = &H[n * N_EDGES + w * 32];
            uint32_t bits = 0;
            #pragma unroll
            for (int i = 0; i < 32; i += 4) {
                int4 v = *reinterpret_cast<const int4*>(&p[i]);
                bits |= (v.x > 0 ? 1u : 0u) << i;
                bits |= (v.y > 0 ? 1u : 0u) << (i + 1);
                bits |= (v.z > 0 ? 1u : 0u) << (i + 2);
                bits |= (v.w > 0 ? 1u : 0u) << (i + 3);
            }
            g_hbits[idx] = bits;
        }
    }
}

// ---- Xh = X @ W (tensor, 3-pass hi/lo) FUSED with scores + global max ----
__global__ __launch_bounds__(256) void k_xh_mma(const float* __restrict__ X,
                                                const float* __restrict__ att) {
    __shared__ __align__(16) unsigned short Bh[IN_DIM * 72], Bl[IN_DIM * 72];
    __shared__ float a_s[NUM_HEADS][8];
    __shared__ int sred[NUM_HEADS];
    int t = threadIdx.x, lane = t & 31, w = t >> 5;
    int n0 = blockIdx.x * 128;
    if (t < 64) a_s[t >> 3][t & 7] = att[(t >> 3) * 16 + (t & 7)] + att[(t >> 3) * 16 + 8 + (t & 7)];
    if (t < NUM_HEADS) sred[t] = 0xFF800000;
    for (int i = t; i < 2048; i += 256) {
        int m = i >> 10, r = (i & 1023) >> 3, q = i & 7;
        const __nv_bfloat16* src = (m ? g_wlo : g_whi) + r * 64 + q * 8;
        unsigned short* dst = (m ? Bl : Bh) + r * 72 + q * 8;
        *reinterpret_cast<uint4*>(dst) = *reinterpret_cast<const uint4*>(src);
    }
    __syncthreads();
    float c[8][4];
    #pragma unroll
    for (int f = 0; f < 8; f++)
        #pragma unroll
        for (int q = 0; q < 4; q++) c[f][q] = 0.f;
    int rbase = n0 + w * 16 + (lane >> 2);
    #pragma unroll
    for (int ks = 0; ks < 8; ks++) {
        int cc = ks * 16 + (lane & 3) * 2;
        float2 z = make_float2(0.f, 0.f);
        float2 x00 = rbase < N_NODES ? *reinterpret_cast<const float2*>(&X[rbase * 128 + cc]) : z;
        float2 x10 = rbase + 8 < N_NODES ? *reinterpret_cast<const float2*>(&X[(rbase + 8) * 128 + cc]) : z;
        float2 x01 = rbase < N_NODES ? *reinterpret_cast<const float2*>(&X[rbase * 128 + cc + 8]) : z;
        float2 x11 = rbase + 8 < N_NODES ? *reinterpret_cast<const float2*>(&X[(rbase + 8) * 128 + cc + 8]) : z;
        uint32_t ah[4], al[4];
        split2(x00, ah[0], al[0]); split2(x10, ah[1], al[1]);
        split2(x01, ah[2], al[2]); split2(x11, ah[3], al[3]);
        int brow = ks * 16 + (lane & 15);
        #pragma unroll
        for (int nf = 0; nf < 4; nf++) {
            uint32_t bh[4], bl[4];
            ldsm4t(bh, smaddr(&Bh[brow * 72 + nf * 16 + (lane >> 4) * 8]));
            ldsm4t(bl, smaddr(&Bl[brow * 72 + nf * 16 + (lane >> 4) * 8]));
            mma16816(c[2 * nf], ah, bh);
            mma16816(c[2 * nf], ah, bl);
            mma16816(c[2 * nf], al, bh);
            mma16816(c[2 * nf + 1], ah, bh + 2);
            mma16816(c[2 * nf + 1], ah, bl + 2);
            mma16816(c[2 * nf + 1], al, bh + 2);
        }
    }
    // store Xh
    #pragma unroll
    for (int f = 0; f < 8; f++) {
        int j = f * 8 + (lane & 3) * 2;
        if (rbase < N_NODES)
            *reinterpret_cast<float2*>(&g_xh[rbase * 64 + j]) = make_float2(c[f][0], c[f][1]);
        if (rbase + 8 < N_NODES)
            *reinterpret_cast<float2*>(&g_xh[(rbase + 8) * 64 + j]) = make_float2(c[f][2], c[f][3]);
    }
    // fused scores: cols f*8..f*8+7 == head f; quad-reduce over (lane&3)
    #pragma unroll
    for (int f = 0; f < 8; f++) {
        float a0 = a_s[f][(lane & 3) * 2], a1 = a_s[f][(lane & 3) * 2 + 1];
        float p0 = c[f][0] * a0 + c[f][1] * a1;
        float p1 = c[f][2] * a0 + c[f][3] * a1;
        p0 += __shfl_xor_sync(0xffffffffu, p0, 1);
        p0 += __shfl_xor_sync(0xffffffffu, p0, 2);
        p1 += __shfl_xor_sync(0xffffffffu, p1, 1);
        p1 += __shfl_xor_sync(0xffffffffu, p1, 2);
        if ((lane & 3) == 0) {
            if (rbase < N_NODES) {
                float s = p0 > 0.f ? p0 : ALPHA * p0;
                g_s[rbase * 8 + f] = s;
                if (s >= 0.f) atomicMax(&sred[f], __float_as_int(s));
                else          atomicMin((unsigned int*)&sred[f], __float_as_uint(s));
            }
            if (rbase + 8 < N_NODES) {
                float s = p1 > 0.f ? p1 : ALPHA * p1;
                g_s[(rbase + 8) * 8 + f] = s;
                if (s >= 0.f) atomicMax(&sred[f], __float_as_int(s));
                else          atomicMin((unsigned int*)&sred[f], __float_as_uint(s));
            }
        }
    }
    __syncthreads();
    if (t < NUM_HEADS) {
        float s = __int_as_float(sred[t]);
        if (s >= 0.f) atomicMax(&g_maxbits[t], __float_as_int(s));
        else          atomicMin((unsigned int*)&g_maxbits[t], __float_as_uint(s));
    }
}

// V (transposed, j-major): rows 0..7 expn, 8..71 expn*Xh; hi/lo bf16
__global__ void k_v() {
    int n = blockIdx.x * 256 + threadIdx.x;
    if (n >= N_NODES) return;
    float ex[8];
    #pragma unroll
    for (int h = 0; h < 8; h++)
        ex[h] = expf(g_s[n * 8 + h] - __int_as_float(g_maxbits[h]));
    #pragma unroll 8
    for (int c = 0; c < 72; c++) {
        float v = (c < 8) ? ex[c] : ex[(c - 8) >> 3] * g_xh[n * 64 + (c - 8)];
        __nv_bfloat16 hi = __float2bfloat16(v);
        g_vhi[c * N_NODES + n] = hi;
        g_vlo[c * N_NODES + n] = __float2bfloat16(v - __bfloat162float(hi));
    }
}

// -------- GEMM1: part[split][j][e] = V2^T(80 x 800) @ H(800 x 128e) --------
// single barrier per chunk: H expansion for ch+1 overlaps mma of ch
__global__ __launch_bounds__(320) void k_edge_mma() {
    int eb = blockIdx.x & 31, split = blockIdx.x >> 5;
    int e0 = eb * 128;
    int t = threadIdx.x, lane = t & 31, w = t >> 5;
    int wm = w % 5, wn = w / 5;
    __shared__ __align__(16) unsigned short Ahi[2][MROWS * 40], Alo[2][MROWS * 40];
    __shared__ __align__(16) unsigned short Hsm[2][32 * 136];

    float c[8][4];
    #pragma unroll
    for (int f = 0; f < 8; f++)
        #pragma unroll
        for (int q = 0; q < 4; q++) c[f][q] = 0.f;

    int nb0 = split * NPS;
    auto loadA = [&](int buf, int nb) {
        for (int o = t; o < 640; o += 320) {
            int j = o >> 3, m = (o >> 2) & 1, q = o & 3;
            const __nv_bfloat16* src = (m ? g_vlo : g_vhi) + j * N_NODES + nb + q * 8;
            unsigned short* dst = (m ? Alo[buf] : Ahi[buf]) + j * 40 + q * 8;
            cpa16(smaddr(dst), src);
        }
    };
    int wordidx = eb * 4 + (t & 3);
    bool wok = (t < 128) && (wordidx < HW_WORDS);
    auto expand = [&](int buf, uint32_t hw) {
        if (t < 128) {
            unsigned short* hb = &Hsm[buf][(t >> 2) * 136 + (t & 3) * 32];
            #pragma unroll
            for (int i = 0; i < 16; i++) {
                uint32_t v = (((hw >> (2 * i)) & 1u) ? 0x3F80u : 0u) |
                             (((hw >> (2 * i + 1)) & 1u) ? 0x3F800000u : 0u);
                *reinterpret_cast<uint32_t*>(hb + 2 * i) = v;
            }
        }
    };
    uint32_t hw = wok ? g_hbits[(nb0 + (t >> 2)) * HW_WORDS + wordidx] : 0u;
    loadA(0, nb0);
    cp_commit();
    expand(0, hw);
    hw = wok ? g_hbits[(nb0 + 32 + (t >> 2)) * HW_WORDS + wordidx] : 0u;
    cp_wait0();
    __syncthreads();

    for (int ch = 0; ch < 25; ch++) {
        int b0 = ch & 1;
        if (ch < 24) { loadA(b0 ^ 1, nb0 + (ch + 1) * 32); cp_commit(); }
        #pragma unroll
        for (int ks = 0; ks < 2; ks++) {
            uint32_t ah[4], al[4];
            int arow = wm * 16 + (lane & 15);
            int acol = ks * 16 + (lane >> 4) * 8;
            ldsm4(ah, smaddr(&Ahi[b0][arow * 40 + acol]));
            ldsm4(al, smaddr(&Alo[b0][arow * 40 + acol]));
            int brow = ks * 16 + (lane & 15);
            #pragma unroll
            for (int nf = 0; nf < 4; nf++) {
                uint32_t b[4];
                ldsm4t(b, smaddr(&Hsm[b0][brow * 136 + wn * 64 + nf * 16 + (lane >> 4) * 8]));
                mma16816(c[2 * nf],     ah, b);
                mma16816(c[2 * nf],     al, b);
                mma16816(c[2 * nf + 1], ah, b + 2);
                mma16816(c[2 * nf + 1], al, b + 2);
            }
        }
        if (ch < 24) {
            expand(b0 ^ 1, hw);
            hw = (ch + 2 < 25 && wok) ?
                g_hbits[(nb0 + (ch + 2) * 32 + (t >> 2)) * HW_WORDS + wordidx] : 0u;
            cp_wait0();
        }
        __syncthreads();
    }
    int jr = wm * 16 + (lane >> 2);
    int ebase = e0 + wn * 64 + (lane & 3) * 2;
    #pragma unroll
    for (int nf = 0; nf < 4; nf++)
        #pragma unroll
        for (int half = 0; half < 2; half++) {
            int f = 2 * nf + half;
            int e = ebase + nf * 16 + half * 8;
            *reinterpret_cast<float2*>(&g_part[(split * MROWS + jr) * EPAD + e]) =
                make_float2(c[f][0], c[f][1]);
            *reinterpret_cast<float2*>(&g_part[(split * MROWS + jr + 8) * EPAD + e]) =
                make_float2(c[f][2], c[f][3]);
        }
}

// -------- reduce partials + agg = num/den + hi/lo split --------
__global__ void k_agg() {
    __shared__ float num[64][65];
    __shared__ float den[64][9];
    int e0 = blockIdx.x * 64;
    int t = threadIdx.x;
    for (int idx = t; idx < 64 * 72; idx += 256) {
        int e_l = idx & 63, col = idx >> 6;
        float s = 0.f;
        #pragma unroll
        for (int sp = 0; sp < NS; sp++)
            s += g_part[(sp * MROWS + col) * EPAD + e0 + e_l];
        if (col < 8) den[e_l][col] = s; else num[e_l][col - 8] = s;
    }
    __syncthreads();
    for (int idx = t; idx < 4096; idx += 256) {
        int j = idx & 63, e_l = idx >> 6;
        int e = e0 + e_l;
        if (e < N_EDGES) {
            float d = den[e_l][j >> 3];
            float v = (d > 0.f) ? num[e_l][j] / d : 0.f;
            __nv_bfloat16 hi = __float2bfloat16(v);
            g_agghi[e * 64 + j] = hi;
            g_agglo[e * 64 + j] = __float2bfloat16(v - __bfloat162float(hi));
        }
    }
}

// -------- GEMM2: opart[split][n][j] = H(128n x 800e) @ agg2(800e x 64j) --------
__global__ __launch_bounds__(256) void k_out_mma() {
    int nbk = blockIdx.x % NB2, split = blockIdx.x / NB2;
    int n0 = nbk * 128;
    int eb0 = split * 800;
    int t = threadIdx.x, lane = t & 31, w = t >> 5;
    __shared__ __align__(16) unsigned short Hsm[2][128 * 40];
    __shared__ __align__(16) unsigned short Bh[2][32 * 72], Bl[2][32 * 72];

    float c[8][4];
    #pragma unroll
    for (int f = 0; f < 8; f++)
        #pragma unroll
        for (int q = 0; q < 4; q++) c[f][q] = 0.f;

    auto loadB = [&](int buf, int e0) {
        for (int o = t; o < 512; o += 256) {
            int r = o >> 4, m = (o >> 3) & 1, q = o & 7;
            const __nv_bfloat16* src = (m ? g_agglo : g_agghi) + (e0 + r) * 64 + q * 8;
            unsigned short* dst = (m ? Bl[buf] : Bh[buf]) + r * 72 + q * 8;
            cpa16(smaddr(dst), src);
        }
    };
    int nrow = n0 + t;
    bool wok = (t < 128) && (nrow < N_NODES);
    auto expand = [&](int buf, uint32_t hw) {
        if (t < 128) {
            unsigned short* hb = &Hsm[buf][t * 40];
            #pragma unroll
            for (int i = 0; i < 16; i++) {
                uint32_t v = (((hw >> (2 * i)) & 1u) ? 0x3F80u : 0u) |
                             (((hw >> (2 * i + 1)) & 1u) ? 0x3F800000u : 0u);
                *reinterpret_cast<uint32_t*>(hb + 2 * i) = v;
            }
        }
    };
    uint32_t hw = wok ? g_hbits[nrow * HW_WORDS + split * 25] : 0u;
    loadB(0, eb0);
    cp_commit();
    expand(0, hw);
    hw = wok ? g_hbits[nrow * HW_WORDS + split * 25 + 1] : 0u;
    cp_wait0();
    __syncthreads();

    for (int ch = 0; ch < 25; ch++) {
        int b0 = ch & 1;
        if (ch < 24) { loadB(b0 ^ 1, eb0 + (ch + 1) * 32); cp_commit(); }
        #pragma unroll
        for (int ks = 0; ks < 2; ks++) {
            uint32_t a[4];
            int arow = w * 16 + (lane & 15);
            ldsm4(a, smaddr(&Hsm[b0][arow * 40 + ks * 16 + (lane >> 4) * 8]));
            int brow = ks * 16 + (lane & 15);
            #pragma unroll
            for (int nf = 0; nf < 4; nf++) {
                uint32_t bh[4], bl[4];
                ldsm4t(bh, smaddr(&Bh[b0][brow * 72 + nf * 16 + (lane >> 4) * 8]));
                ldsm4t(bl, smaddr(&Bl[b0][brow * 72 + nf * 16 + (lane >> 4) * 8]));
                mma16816(c[2 * nf],     a, bh);
                mma16816(c[2 * nf],     a, bl);
                mma16816(c[2 * nf + 1], a, bh + 2);
                mma16816(c[2 * nf + 1], a, bl + 2);
            }
        }
        if (ch < 24) {
            expand(b0 ^ 1, hw);
            hw = (ch + 2 < 25 && wok) ?
                g_hbits[nrow * HW_WORDS + split * 25 + ch + 2] : 0u;
            cp_wait0();
        }
        __syncthreads();
    }
    int n = n0 + w * 16 + (lane >> 2);
    #pragma unroll
    for (int nf = 0; nf < 4; nf++)
        #pragma unroll
        for (int half = 0; half < 2; half++) {
            int f = 2 * nf + half, j = nf * 16 + half * 8 + (lane & 3) * 2;
            if (n < N_NODES)
                *reinterpret_cast<float2*>(&g_opart[(split * N_NODES + n) * 64 + j]) =
                    make_float2(c[f][0], c[f][1]);
            if (n + 8 < N_NODES)
                *reinterpret_cast<float2*>(&g_opart[(split * N_NODES + n + 8) * 64 + j]) =
                    make_float2(c[f][2], c[f][3]);
        }
}

// -------- finalize: fixed-order split reduce + bias (bounds-guarded) --------
__global__ void k_final(const float* __restrict__ bias, float* __restrict__ out) {
    int i = blockIdx.x * 256 + threadIdx.x;
    if (i >= N_NODES * OUT_DIM / 4) return;
    float4 s = *reinterpret_cast<const float4*>(&bias[(i & 15) * 4]);
    #pragma unroll
    for (int sp = 0; sp < KS2; sp++) {
        float4 v = *reinterpret_cast<const float4*>(&g_opart[sp * N_NODES * OUT_DIM + i * 4]);
        s.x += v.x; s.y += v.y; s.z += v.z; s.w += v.w;
    }
    *reinterpret_cast<float4*>(&out[i * 4]) = s;
}

// ---------------- launch ----------------
extern "C" void kernel_launch(void* const* d_in, const int* in_sizes, int n_in,
                              void* d_out, int out_size) {
    const float* X    = (const float*)d_in[0];
    const int*   H    = (const int*)  d_in[1];
    const float* W    = (const float*)d_in[2];
    const float* att  = (const float*)d_in[3];
    const float* bias = (const float*)d_in[4];
    float* out = (float*)d_out;

    int prep_blocks = PREP_WBLKS + (N_NODES * HW_WORDS + 255) / 256;
    k_prep    <<<prep_blocks, 256>>>(H, W);                 // launch 1
    k_xh_mma  <<<NB2, 256>>>(X, att);                       // launch 2 (+scores)
    k_v       <<<(N_NODES + 255) / 256, 256>>>();           // launch 3
    k_edge_mma<<<NS * 32, 320>>>();                         // launch 4 (profiled)
    k_agg     <<<(N_EDGES + 63) / 64, 256>>>();             // launch 5
    k_out_mma <<<KS2 * NB2, 256>>>();                       // launch 6
    k_final   <<<(N_NODES * OUT_DIM / 4 + 255) / 256, 256>>>(bias, out);  // launch 7
}